// round 4
// baseline (speedup 1.0000x reference)
#include <cuda_runtime.h>
#include <cuda_bf16.h>

// Fixed shapes: B=2, C=16, D=64, H=128, W=128
#define NVOX   (64 * 128 * 128)          // 1,048,576 voxels per batch
#define NCLS   16
#define NB     2
#define THREADS 256
#define BLOCKS_PER_BATCH 444
#define NBLOCKS (NB * BLOCKS_PER_BATCH)      // 888 = 148 SMs x 6 blocks
#define QPI    (BLOCKS_PER_BATCH * THREADS)  // 113,664 quads per iteration
#define TAIL_BLOCKS 136                      // iter 2 covers exactly 136 blocks

// Device-global scratch (zero-init at load; last block re-zeros post-finalize).
__device__ float    g_sum[NB * NCLS];
__device__ float    g_cnt[NB * NCLS];
__device__ unsigned g_ticket;

__global__ __launch_bounds__(THREADS, 6)
void ce_fused_kernel(const float* __restrict__ x, const void* __restrict__ y,
                     float* __restrict__ out) {
    // Per-thread private nll bins; bank = tid%32 -> conflict-free RMW.
    __shared__ float s_bin[NCLS][THREADS];
    __shared__ int   sh_y64;
    __shared__ int   sh_last;

    const int tid      = threadIdx.x;
    const int blk      = blockIdx.x;
    const int b        = (blk >= BLOCKS_PER_BATCH) ? 1 : 0;
    const int blk_in_b = blk - b * BLOCKS_PER_BATCH;
    const float* xb = x + (size_t)b * NCLS * NVOX;

#pragma unroll
    for (int c = 0; c < NCLS; c++) s_bin[c][tid] = 0.0f;

    // Label dtype detect: int64 (LE) => every odd int32 word is 0 (labels<16).
    if (tid < 32) {
        int v = ((const int*)y)[2 * tid + 1];
        unsigned nz = __ballot_sync(0xffffffffu, v != 0);
        if (tid == 0) sh_y64 = (nz == 0u) ? 1 : 0;
    }
    __syncthreads();
    const bool y64 = (sh_y64 != 0);

    // Counts: 16 classes x 4-bit nibbles in one 64-bit reg (max 12 per class).
    unsigned long long cnt64 = 0ull;

#pragma unroll
    for (int it = 0; it < 3; it++) {
        if (it == 2 && blk_in_b >= TAIL_BLOCKS) break;   // block-uniform
        const int n = (it * QPI + blk_in_b * THREADS + tid) * 4;

        int lab0, lab1, lab2, lab3;
        if (y64) {
            const longlong2* yp =
                (const longlong2*)((const long long*)y + (size_t)b * NVOX + n);
            longlong2 l0 = yp[0];
            longlong2 l1 = yp[1];
            lab0 = (int)l0.x; lab1 = (int)l0.y;
            lab2 = (int)l1.x; lab3 = (int)l1.y;
        } else {
            int4 l = *(const int4*)((const int*)y + (size_t)b * NVOX + n);
            lab0 = l.x; lab1 = l.y; lab2 = l.z; lab3 = l.w;
        }

        float s0 = 0.f, s1 = 0.f, s2 = 0.f, s3 = 0.f;
        float xl0 = 0.f, xl1 = 0.f, xl2 = 0.f, xl3 = 0.f;
        const float* xp = xb + n;

        // 4 groups of 4 staged float4 loads -> MLP >= 4 per thread.
#pragma unroll
        for (int g = 0; g < 4; g++) {
            const float4 va = *(const float4*)(xp + (size_t)(4 * g + 0) * NVOX);
            const float4 vb = *(const float4*)(xp + (size_t)(4 * g + 1) * NVOX);
            const float4 vc = *(const float4*)(xp + (size_t)(4 * g + 2) * NVOX);
            const float4 vd = *(const float4*)(xp + (size_t)(4 * g + 3) * NVOX);

#define PROC(v, cc)                                                        \
            s0 += __expf((v).x); s1 += __expf((v).y);                      \
            s2 += __expf((v).z); s3 += __expf((v).w);                      \
            if (lab0 == (cc)) xl0 = (v).x;                                 \
            if (lab1 == (cc)) xl1 = (v).y;                                 \
            if (lab2 == (cc)) xl2 = (v).z;                                 \
            if (lab3 == (cc)) xl3 = (v).w;

            PROC(va, 4 * g + 0)
            PROC(vb, 4 * g + 1)
            PROC(vc, 4 * g + 2)
            PROC(vd, 4 * g + 3)
#undef PROC
        }

        const float nll0 = __logf(s0) - xl0;
        const float nll1 = __logf(s1) - xl1;
        const float nll2 = __logf(s2) - xl2;
        const float nll3 = __logf(s3) - xl3;

        s_bin[lab0][tid] += nll0;
        s_bin[lab1][tid] += nll1;
        s_bin[lab2][tid] += nll2;
        s_bin[lab3][tid] += nll3;
        cnt64 += (1ull << (lab0 * 4)) + (1ull << (lab1 * 4))
               + (1ull << (lab2 * 4)) + (1ull << (lab3 * 4));
    }
    __syncthreads();

    // Phase 1: reduce nll bins. Warp w handles labs {w, w+8}.
    const int w = tid >> 5, l = tid & 31;
#pragma unroll
    for (int lab = w; lab < NCLS; lab += 8) {
        float fs = 0.0f;
#pragma unroll
        for (int k = 0; k < 8; k++) fs += s_bin[lab][l + 32 * k];
#pragma unroll
        for (int o = 16; o > 0; o >>= 1)
            fs += __shfl_xor_sync(0xffffffffu, fs, o);
        if (l == 0) atomicAdd(&g_sum[b * NCLS + lab], fs);
    }
    __syncthreads();

    // Phase 2: reuse s_bin for counts (thread-private slots: plain stores).
#pragma unroll
    for (int c = 0; c < NCLS; c++)
        s_bin[c][tid] = (float)(int)((cnt64 >> (c * 4)) & 0xfull);
    __syncthreads();
#pragma unroll
    for (int lab = w; lab < NCLS; lab += 8) {
        float fs = 0.0f;
#pragma unroll
        for (int k = 0; k < 8; k++) fs += s_bin[lab][l + 32 * k];
#pragma unroll
        for (int o = 16; o > 0; o >>= 1)
            fs += __shfl_xor_sync(0xffffffffu, fs, o);
        if (l == 0) atomicAdd(&g_cnt[b * NCLS + lab], fs);
    }

    // Last-block finalize.
    __threadfence();
    if (tid == 0) {
        unsigned t = atomicAdd(&g_ticket, 1u);
        sh_last = (t == (unsigned)(NBLOCKS - 1)) ? 1 : 0;
    }
    __syncthreads();

    if (sh_last) {
        __threadfence();
        if (tid < NB * NCLS) {
            const float s = atomicAdd(&g_sum[tid], 0.0f);
            const float c = atomicAdd(&g_cnt[tid], 0.0f);
            float m = (c > 0.0f) ? (s / c) : 0.0f;
#pragma unroll
            for (int o = 16; o > 0; o >>= 1)
                m += __shfl_xor_sync(0xffffffffu, m, o);
            if (tid == 0) {
                out[0] = m / (float)(NB * NCLS);
                g_ticket = 0u;
            }
            g_sum[tid] = 0.0f;
            g_cnt[tid] = 0.0f;
        }
    }
}

extern "C" void kernel_launch(void* const* d_in, const int* in_sizes, int n_in,
                              void* d_out, int out_size) {
    const float* x = (const float*)d_in[0];
    const void*  y = d_in[1];
    ce_fused_kernel<<<NBLOCKS, THREADS>>>(x, y, (float*)d_out);
}

// round 5
// speedup vs baseline: 1.0141x; 1.0141x over previous
#include <cuda_runtime.h>
#include <cuda_bf16.h>

// Fixed shapes: B=2, C=16, D=64, H=128, W=128
#define NVOX   (64 * 128 * 128)          // 1,048,576 voxels per batch
#define NCLS   16
#define NB     2
#define THREADS 256
#define BLOCKS_PER_BATCH 444
#define NBLOCKS (NB * BLOCKS_PER_BATCH)      // 888 = 148 SMs x 6 blocks
#define QPI    (BLOCKS_PER_BATCH * THREADS)  // 113,664 quads per iteration
#define TAIL_BLOCKS 136                      // iter 2 covers exactly 136 blocks

// Device-global scratch (zero-init at load; last block re-zeros post-finalize).
__device__ float    g_sum[NB * NCLS];
__device__ float    g_cnt[NB * NCLS];
__device__ unsigned g_ticket;

__global__ __launch_bounds__(THREADS, 6)
void ce_fused_kernel(const float* __restrict__ x, const void* __restrict__ y,
                     float* __restrict__ out) {
    // Per-thread private nll bins; word = lab*256+tid -> bank tid%32, no conflicts.
    __shared__ float s_bin[NCLS][THREADS];
    __shared__ int   sh_y64;
    __shared__ int   sh_last;

    const int tid      = threadIdx.x;
    const int blk      = blockIdx.x;
    const int b        = (blk >= BLOCKS_PER_BATCH) ? 1 : 0;
    const int blk_in_b = blk - b * BLOCKS_PER_BATCH;
    const float* xb = x + (size_t)b * NCLS * NVOX;

#pragma unroll
    for (int c = 0; c < NCLS; c++) s_bin[c][tid] = 0.0f;

    // Label dtype detect: int64 (LE) => every odd int32 word is 0 (labels<16).
    if (tid < 32) {
        int v = ((const int*)y)[2 * tid + 1];
        unsigned nz = __ballot_sync(0xffffffffu, v != 0);
        if (tid == 0) sh_y64 = (nz == 0u) ? 1 : 0;
    }
    __syncthreads();
    const bool y64 = (sh_y64 != 0);

    // Counts: 16 classes x 4-bit nibbles in one 64-bit reg (max 12 per class).
    unsigned long long cnt64 = 0ull;

#pragma unroll
    for (int it = 0; it < 3; it++) {
        if (it == 2 && blk_in_b >= TAIL_BLOCKS) break;   // block-uniform
        const int n = (it * QPI + blk_in_b * THREADS + tid) * 4;

        int lab0, lab1, lab2, lab3;
        if (y64) {
            const longlong2* yp =
                (const longlong2*)((const long long*)y + (size_t)b * NVOX + n);
            longlong2 l0 = yp[0];
            longlong2 l1 = yp[1];
            lab0 = (int)l0.x; lab1 = (int)l0.y;
            lab2 = (int)l1.x; lab3 = (int)l1.y;
        } else {
            int4 l = *(const int4*)((const int*)y + (size_t)b * NVOX + n);
            lab0 = l.x; lab1 = l.y; lab2 = l.z; lab3 = l.w;
        }

        const float* xp = xb + n;

        // Direct gather of the label logits — replaces 128 ISETP/FSEL ops.
        // Same cache lines the sweep below reads: no extra DRAM traffic, and
        // issued first so they overlap the entire sweep.
        const float xl0 = xp[(size_t)lab0 * NVOX + 0];
        const float xl1 = xp[(size_t)lab1 * NVOX + 1];
        const float xl2 = xp[(size_t)lab2 * NVOX + 2];
        const float xl3 = xp[(size_t)lab3 * NVOX + 3];

        // Pure log-sum-exp sweep: only s0..s3 live across the unroll, so
        // ptxas can pipeline the 16 LDG.128 deep ahead of consumption.
        float s0 = 0.f, s1 = 0.f, s2 = 0.f, s3 = 0.f;
#pragma unroll
        for (int c = 0; c < NCLS; c++) {
            const float4 v = *(const float4*)(xp + (size_t)c * NVOX);
            s0 += __expf(v.x);
            s1 += __expf(v.y);
            s2 += __expf(v.z);
            s3 += __expf(v.w);
        }

        const float nll0 = __logf(s0) - xl0;
        const float nll1 = __logf(s1) - xl1;
        const float nll2 = __logf(s2) - xl2;
        const float nll3 = __logf(s3) - xl3;

        s_bin[lab0][tid] += nll0;
        s_bin[lab1][tid] += nll1;
        s_bin[lab2][tid] += nll2;
        s_bin[lab3][tid] += nll3;
        cnt64 += (1ull << (lab0 * 4)) + (1ull << (lab1 * 4))
               + (1ull << (lab2 * 4)) + (1ull << (lab3 * 4));
    }
    __syncthreads();

    // Phase 1: reduce nll bins. Warp w handles labs {w, w+8}.
    const int w = tid >> 5, l = tid & 31;
#pragma unroll
    for (int lab = w; lab < NCLS; lab += 8) {
        float fs = 0.0f;
#pragma unroll
        for (int k = 0; k < 8; k++) fs += s_bin[lab][l + 32 * k];
#pragma unroll
        for (int o = 16; o > 0; o >>= 1)
            fs += __shfl_xor_sync(0xffffffffu, fs, o);
        if (l == 0) atomicAdd(&g_sum[b * NCLS + lab], fs);
    }
    __syncthreads();

    // Phase 2: reuse s_bin for counts (thread-private slots: plain stores).
#pragma unroll
    for (int c = 0; c < NCLS; c++)
        s_bin[c][tid] = (float)(int)((cnt64 >> (c * 4)) & 0xfull);
    __syncthreads();
#pragma unroll
    for (int lab = w; lab < NCLS; lab += 8) {
        float fs = 0.0f;
#pragma unroll
        for (int k = 0; k < 8; k++) fs += s_bin[lab][l + 32 * k];
#pragma unroll
        for (int o = 16; o > 0; o >>= 1)
            fs += __shfl_xor_sync(0xffffffffu, fs, o);
        if (l == 0) atomicAdd(&g_cnt[b * NCLS + lab], fs);
    }

    // Last-block finalize.
    __threadfence();
    if (tid == 0) {
        unsigned t = atomicAdd(&g_ticket, 1u);
        sh_last = (t == (unsigned)(NBLOCKS - 1)) ? 1 : 0;
    }
    __syncthreads();

    if (sh_last) {
        __threadfence();
        if (tid < NB * NCLS) {
            const float s = atomicAdd(&g_sum[tid], 0.0f);
            const float c = atomicAdd(&g_cnt[tid], 0.0f);
            float m = (c > 0.0f) ? (s / c) : 0.0f;
#pragma unroll
            for (int o = 16; o > 0; o >>= 1)
                m += __shfl_xor_sync(0xffffffffu, m, o);
            if (tid == 0) {
                out[0] = m / (float)(NB * NCLS);
                g_ticket = 0u;
            }
            g_sum[tid] = 0.0f;
            g_cnt[tid] = 0.0f;
        }
    }
}

extern "C" void kernel_launch(void* const* d_in, const int* in_sizes, int n_in,
                              void* d_out, int out_size) {
    const float* x = (const float*)d_in[0];
    const void*  y = d_in[1];
    ce_fused_kernel<<<NBLOCKS, THREADS>>>(x, y, (float*)d_out);
}

// round 6
// speedup vs baseline: 1.3878x; 1.3685x over previous
#include <cuda_runtime.h>
#include <cstdint>

// Fixed shapes: B=2, C=16, NVOX = 64*128*128 = 2^20
#define NVOX   (1 << 20)
#define NCLS   16
#define NB     2
#define THREADS 256
#define BLK_PER_B 148
#define NBLK   (NB * BLK_PER_B)            // 296 = exactly 2 blocks/SM, 1 wave
#define TSTG   256                         // voxels per pipeline stage
#define STG_PER_B (NVOX / TSTG)            // 4096 stages per batch
#define XB_BYTES (NCLS * TSTG * 4)         // 16384 B of logits per stage
#define STAGE_BYTES (XB_BYTES + TSTG * 8)  // + up to 2KB labels = 18432
#define NBUF   4
#define DYN_BYTES (NBUF * STAGE_BYTES)     // 73728

// Device-global scratch (zero-init at load; last block re-zeros post-finalize).
__device__ float    g_sum[NB * NCLS];
__device__ float    g_cnt[NB * NCLS];
__device__ unsigned g_ticket;

extern __shared__ char dynsmem[];

__device__ __forceinline__ void cp16(uint32_t dst, const void* src) {
    asm volatile("cp.async.cg.shared.global [%0], [%1], 16;" :: "r"(dst), "l"(src));
}

__global__ __launch_bounds__(THREADS, 2)
void ce_pipe_kernel(const float* __restrict__ x, const char* __restrict__ y,
                    float* __restrict__ out) {
    __shared__ float s_bin[NCLS][THREADS];   // bank = tid%32 -> conflict-free
    __shared__ int   sh_y64, sh_last;

    const int tid = threadIdx.x;
    const int blk = blockIdx.x;
    const int b   = (blk >= BLK_PER_B) ? 1 : 0;
    const int bb  = blk - b * BLK_PER_B;
    const uint32_t smem_u32 = (uint32_t)__cvta_generic_to_shared(dynsmem);

#pragma unroll
    for (int c = 0; c < NCLS; c++) s_bin[c][tid] = 0.0f;

    // Label dtype detect: int64 (LE) => every odd int32 word is 0 (labels<16).
    if (tid < 32) {
        int v = ((const int*)y)[2 * tid + 1];
        unsigned nz = __ballot_sync(0xffffffffu, v != 0);
        if (tid == 0) sh_y64 = (nz == 0u) ? 1 : 0;
    }
    __syncthreads();
    const bool y64 = (sh_y64 != 0);

    // Stages owned by this block: sl = bb + i*148 < 4096 (27 or 28 of them).
    const int nIter = (STG_PER_B - bb + BLK_PER_B - 1) / BLK_PER_B;
    const float* xb = x + (size_t)b * NCLS * NVOX;
    const char*  yb = y + ((size_t)b * NVOX << (y64 ? 3 : 2));

    auto issue = [&](int i) {
        const int sl  = bb + i * BLK_PER_B;
        const int off = sl * TSTG;
        const uint32_t sb = smem_u32 + (uint32_t)(i & 3) * STAGE_BYTES;
        const int lane64 = tid & 63, grp = tid >> 6;
#pragma unroll
        for (int r = 0; r < 4; r++) {
            const int c = 4 * r + grp;   // 64 threads copy one 1KB class row
            cp16(sb + (uint32_t)(c * (TSTG * 4) + lane64 * 16),
                 xb + (size_t)c * NVOX + off + lane64 * 4);
        }
        if (y64) {
            if (tid < 128)
                cp16(sb + XB_BYTES + tid * 16, yb + (size_t)off * 8 + tid * 16);
        } else {
            if (tid < 64)
                cp16(sb + XB_BYTES + tid * 16, yb + (size_t)off * 4 + tid * 16);
        }
    };

    // Prologue: 3 stages in flight.
#pragma unroll
    for (int k = 0; k < 3; k++) {
        if (k < nIter) issue(k);
        asm volatile("cp.async.commit_group;" ::: "memory");
    }

    // Counts: classes 0-7 in cLo byte lanes, 8-15 in cHi (max 28 <= 255).
    unsigned long long cLo = 0ull, cHi = 0ull;

    for (int i = 0; i < nIter; i++) {
        asm volatile("cp.async.wait_group 2;" ::: "memory");  // stage i landed
        __syncthreads();
        // Refill: writes buffer (i+3)&3 == (i-1)&3, whose compute finished
        // before the syncthreads above. Always commit to keep group count.
        if (i + 3 < nIter) issue(i + 3);
        asm volatile("cp.async.commit_group;" ::: "memory");

        const char*  stg = dynsmem + (size_t)(i & 3) * STAGE_BYTES;
        const float* xt  = (const float*)stg;
        const int lab = y64 ? ((const int*)(stg + XB_BYTES))[2 * tid]
                            : ((const int*)(stg + XB_BYTES))[tid];

        float a0 = 0.f, a1 = 0.f, a2 = 0.f, a3 = 0.f;
#pragma unroll
        for (int c = 0; c < NCLS; c += 4) {
            a0 += __expf(xt[(c + 0) * TSTG + tid]);
            a1 += __expf(xt[(c + 1) * TSTG + tid]);
            a2 += __expf(xt[(c + 2) * TSTG + tid]);
            a3 += __expf(xt[(c + 3) * TSTG + tid]);
        }
        const float xl  = xt[lab * TSTG + tid];          // bank tid%32: clean
        const float nll = __logf((a0 + a1) + (a2 + a3)) - xl;

        s_bin[lab][tid] += nll;
        if (lab < 8) cLo += 1ull << (lab * 8);
        else         cHi += 1ull << ((lab - 8) * 8);
    }
    __syncthreads();

    // Phase 1: reduce nll bins. Warp w handles labs {w, w+8}.
    const int w = tid >> 5, l = tid & 31;
#pragma unroll
    for (int lab = w; lab < NCLS; lab += 8) {
        float fs = 0.0f;
#pragma unroll
        for (int k = 0; k < 8; k++) fs += s_bin[lab][l + 32 * k];
#pragma unroll
        for (int o = 16; o > 0; o >>= 1)
            fs += __shfl_xor_sync(0xffffffffu, fs, o);
        if (l == 0) atomicAdd(&g_sum[b * NCLS + lab], fs);
    }
    __syncthreads();

    // Phase 2: reuse s_bin for counts (thread-private slots: plain stores).
#pragma unroll
    for (int c = 0; c < NCLS; c++) {
        const unsigned cc = (unsigned)(((c < 8 ? cLo : cHi) >> ((c & 7) * 8)) & 0xffull);
        s_bin[c][tid] = (float)cc;
    }
    __syncthreads();
#pragma unroll
    for (int lab = w; lab < NCLS; lab += 8) {
        float fs = 0.0f;
#pragma unroll
        for (int k = 0; k < 8; k++) fs += s_bin[lab][l + 32 * k];
#pragma unroll
        for (int o = 16; o > 0; o >>= 1)
            fs += __shfl_xor_sync(0xffffffffu, fs, o);
        if (l == 0) atomicAdd(&g_cnt[b * NCLS + lab], fs);
    }

    // Last-block finalize.
    __threadfence();
    if (tid == 0) {
        unsigned t = atomicAdd(&g_ticket, 1u);
        sh_last = (t == (unsigned)(NBLK - 1)) ? 1 : 0;
    }
    __syncthreads();

    if (sh_last) {
        __threadfence();
        if (tid < NB * NCLS) {
            const float s = atomicAdd(&g_sum[tid], 0.0f);
            const float c = atomicAdd(&g_cnt[tid], 0.0f);
            float m = (c > 0.0f) ? (s / c) : 0.0f;
#pragma unroll
            for (int o = 16; o > 0; o >>= 1)
                m += __shfl_xor_sync(0xffffffffu, m, o);
            if (tid == 0) {
                out[0] = m / (float)(NB * NCLS);
                g_ticket = 0u;
            }
            g_sum[tid] = 0.0f;
            g_cnt[tid] = 0.0f;
        }
    }
}

extern "C" void kernel_launch(void* const* d_in, const int* in_sizes, int n_in,
                              void* d_out, int out_size) {
    const float* x = (const float*)d_in[0];
    const char*  y = (const char*)d_in[1];
    cudaFuncSetAttribute(ce_pipe_kernel,
                         cudaFuncAttributeMaxDynamicSharedMemorySize, DYN_BYTES);
    ce_pipe_kernel<<<NBLK, THREADS, DYN_BYTES>>>(x, y, (float*)d_out);
}